// round 3
// baseline (speedup 1.0000x reference)
#include <cuda_runtime.h>
#include <cuda_bf16.h>

#define Hh 96
#define Ww 96
#define HW 9216
#define Cc 64
#define Oo 64
#define Bb 4
#define NT 9            // taps per frame
#define ON 576          // Oo*NT

// Scratch: Y[(o*9+n)*B + b][p]  (85 MB)
__device__ float g_Y[(size_t)ON * Bb * HW];
__device__ float g_scale[Oo];
__device__ float g_shift[Oo];

// ---------------------------------------------------------------------------
// Kernel A: Y[o,n,b,p] = sum_c w[o,c,n] * x[b,c,p]
// Block: 4 o's (36 j = oo*9+n), 512 pixels (2 per thread).
// Grid: (HW/512=18, B=4, O/4=16)
// ---------------------------------------------------------------------------
__global__ __launch_bounds__(256) void kA(const float* __restrict__ x,
                                          const float* __restrict__ cw) {
    __shared__ float wsm[36 * 64];

    const int b  = blockIdx.y;
    const int o0 = blockIdx.z * 4;

    for (int idx = threadIdx.x; idx < 36 * 64; idx += 256) {
        int j = idx >> 6, c = idx & 63;
        int oo = j / 9, n = j - oo * 9;
        wsm[c * 36 + j] = cw[(size_t)(o0 + oo) * (Cc * NT) + c * NT + n];
    }
    __syncthreads();

    const int p0 = blockIdx.x * 512 + threadIdx.x;   // second pixel = p0+256
    const float* xb = x + (size_t)b * Cc * HW;

    float acc0[36], acc1[36];
#pragma unroll
    for (int j = 0; j < 36; j++) { acc0[j] = 0.f; acc1[j] = 0.f; }

    for (int c = 0; c < Cc; c++) {
        float a0 = xb[c * HW + p0];
        float a1 = xb[c * HW + p0 + 256];
        const float* wrow = &wsm[c * 36];
#pragma unroll
        for (int j = 0; j < 36; j++) {
            float wv = wrow[j];
            acc0[j] = fmaf(a0, wv, acc0[j]);
            acc1[j] = fmaf(a1, wv, acc1[j]);
        }
    }

#pragma unroll
    for (int j = 0; j < 36; j++) {
        int oo = j / 9, n = j - oo * 9;
        float* Yp = g_Y + (size_t)(((o0 + oo) * NT + n) * Bb + b) * HW;
        Yp[p0]       = acc0[j];
        Yp[p0 + 256] = acc1[j];
    }
}

// ---------------------------------------------------------------------------
// Kernel B: pre-BN output = bias[o] + sum_n bilinear-blend(Y[o,n,b])
// Taps (index pair + weight pair) depend only on (o,n,coord): precompute in smem.
// Grid: (HW/256=36, B=4, O=64)
// ---------------------------------------------------------------------------
struct alignas(16) Tap { int lo; int hi; float wl; float wr; };

__global__ __launch_bounds__(256) void kB(const float* __restrict__ frames,
                                          const float* __restrict__ bias,
                                          float* __restrict__ out) {
    __shared__ Tap SX[NT][Ww];
    __shared__ Tap SY[NT][Hh];

    const int o = blockIdx.z;
    const int b = blockIdx.y;

    // Precompute taps. idx < 864: x-direction; idx >= 864: y-direction.
    for (int idx = threadIdx.x; idx < 2 * NT * 96; idx += 256) {
        int which = (idx >= NT * 96) ? 1 : 0;
        int r = idx - which * (NT * 96);
        int n = r / 96, t = r - n * 96;
        float d  = frames[o * (2 * NT) + which * NT + n]; // first 9: x-offs, last 9: y-offs
        float pf = d + (float)t;                          // matches ref: frame + coord in f32
        float ff = floorf(pf);
        float lof = fminf(fmaxf(ff, 0.f), 95.f);
        float hif = fminf(fmaxf(ff + 1.f, 0.f), 95.f);
        float pc  = fminf(fmaxf(pf, 0.f), 95.f);
        Tap tp;
        tp.lo = (int)lof;
        tp.hi = (int)hif;
        tp.wl = 1.f + lof - pc;   // (1 + (lt - pc))
        tp.wr = 1.f - hif + pc;   // (1 - (rb - pc))
        if (which == 0) SX[n][t] = tp; else SY[n][t] = tp;
    }
    __syncthreads();

    const int p = blockIdx.x * 256 + threadIdx.x;
    const int h = p / Ww, w = p - h * Ww;
    const float* Ybase = g_Y + (size_t)(o * NT * Bb + b) * HW;

    float acc = 0.f;
#pragma unroll
    for (int n = 0; n < NT; n++) {
        Tap tx = SX[n][w];
        Tap ty = SY[n][h];
        const float* Yp = Ybase + (size_t)n * (Bb * HW);
        const float* rT = Yp + ty.lo * Ww;
        const float* rB = Yp + ty.hi * Ww;
        float vT = tx.wl * rT[tx.lo] + tx.wr * rT[tx.hi];
        float vB = tx.wl * rB[tx.lo] + tx.wr * rB[tx.hi];
        acc += ty.wl * vT + ty.wr * vB;
    }
    out[(size_t)(b * Oo + o) * HW + p] = acc + bias[o];
}

// ---------------------------------------------------------------------------
// Kernel C1: per-channel batch stats (biased var) -> scale/shift. Grid: 64 blocks.
// ---------------------------------------------------------------------------
__global__ __launch_bounds__(256) void kC1(const float* __restrict__ out,
                                           const float* __restrict__ gamma,
                                           const float* __restrict__ beta) {
    const int o = blockIdx.x;
    float s = 0.f, s2 = 0.f;
    for (int b = 0; b < Bb; b++) {
        const float* p = out + (size_t)(b * Oo + o) * HW;
        for (int i = threadIdx.x; i < HW; i += 256) {
            float v = p[i];
            s += v;
            s2 += v * v;
        }
    }
    __shared__ float rs[256], rq[256];
    rs[threadIdx.x] = s;
    rq[threadIdx.x] = s2;
    __syncthreads();
    for (int st = 128; st > 0; st >>= 1) {
        if (threadIdx.x < st) {
            rs[threadIdx.x] += rs[threadIdx.x + st];
            rq[threadIdx.x] += rq[threadIdx.x + st];
        }
        __syncthreads();
    }
    if (threadIdx.x == 0) {
        const float inv = 1.f / (float)(Bb * HW);
        float mean = rs[0] * inv;
        float var  = rq[0] * inv - mean * mean;
        float rstd = rsqrtf(var + 1e-5f);
        float sc = gamma[o] * rstd;
        g_scale[o] = sc;
        g_shift[o] = beta[o] - mean * sc;
    }
}

// ---------------------------------------------------------------------------
// Kernel C2: in-place normalize + ReLU. Grid: 9216 blocks of 256.
// ---------------------------------------------------------------------------
__global__ __launch_bounds__(256) void kC2(float* __restrict__ out) {
    const int idx = blockIdx.x * 256 + threadIdx.x;
    const int o = (idx / HW) & 63;
    float v = out[idx];
    out[idx] = fmaxf(fmaf(v, g_scale[o], g_shift[o]), 0.f);
}

extern "C" void kernel_launch(void* const* d_in, const int* in_sizes, int n_in,
                              void* d_out, int out_size) {
    const float* x      = (const float*)d_in[0];
    const float* frames = (const float*)d_in[1];
    const float* cw     = (const float*)d_in[2];
    const float* cb     = (const float*)d_in[3];
    const float* gamma  = (const float*)d_in[4];
    const float* beta   = (const float*)d_in[5];
    float* out = (float*)d_out;

    kA<<<dim3(HW / 512, Bb, Oo / 4), 256>>>(x, cw);
    kB<<<dim3(HW / 256, Bb, Oo), 256>>>(frames, cb, out);
    kC1<<<Oo, 256>>>(out, gamma, beta);
    kC2<<<(Bb * Oo * HW) / 256, 256>>>(out);
}

// round 7
// speedup vs baseline: 1.1495x; 1.1495x over previous
#include <cuda_runtime.h>
#include <cuda_bf16.h>

#define Hh 96
#define Ww 96
#define HW 9216
#define Cc 64
#define Oo 64
#define Bb 4
#define NT 9            // taps per frame
#define ON 576          // Oo*NT
#define NBX 36          // kB blocks per (b,o) image

// Scratch: Y[(o*9+n)*B + b][p]  (85 MB)
__device__ float g_Y[(size_t)ON * Bb * HW];
__device__ float g_scale[Oo];
__device__ float g_shift[Oo];
__device__ float g_psum[Oo * Bb * NBX];
__device__ float g_psq [Oo * Bb * NBX];

// ---------------------------------------------------------------------------
// Kernel A: Y[o,n,b,p] = sum_c w[o,c,n] * x[b,c,p]
// Block: 4 o's (36 j = oo*9+n), 512 pixels (2 per thread).
// Weights in smem laid out [c][36] so the j-loop reads float4 (LDS.128).
// Grid: (HW/512=18, B=4, O/4=16)
// ---------------------------------------------------------------------------
__global__ __launch_bounds__(256) void kA(const float* __restrict__ x,
                                          const float* __restrict__ cw) {
    __shared__ alignas(16) float wsm[64 * 36];   // [c][j], row = 144B (16B aligned)

    const int b  = blockIdx.y;
    const int o0 = blockIdx.z * 4;

    for (int idx = threadIdx.x; idx < 36 * 64; idx += 256) {
        int j = idx >> 6, c = idx & 63;
        int oo = j / 9, n = j - oo * 9;
        wsm[c * 36 + j] = cw[(size_t)(o0 + oo) * (Cc * NT) + c * NT + n];
    }
    __syncthreads();

    const int p0 = blockIdx.x * 512 + threadIdx.x;   // second pixel = p0+256
    const float* xb = x + (size_t)b * Cc * HW;

    float acc0[36], acc1[36];
#pragma unroll
    for (int j = 0; j < 36; j++) { acc0[j] = 0.f; acc1[j] = 0.f; }

#pragma unroll 2
    for (int c = 0; c < Cc; c++) {
        float a0 = xb[c * HW + p0];
        float a1 = xb[c * HW + p0 + 256];
        const float4* wrow = reinterpret_cast<const float4*>(&wsm[c * 36]);
#pragma unroll
        for (int q = 0; q < 9; q++) {
            float4 w4 = wrow[q];
            acc0[q*4+0] = fmaf(a0, w4.x, acc0[q*4+0]);
            acc1[q*4+0] = fmaf(a1, w4.x, acc1[q*4+0]);
            acc0[q*4+1] = fmaf(a0, w4.y, acc0[q*4+1]);
            acc1[q*4+1] = fmaf(a1, w4.y, acc1[q*4+1]);
            acc0[q*4+2] = fmaf(a0, w4.z, acc0[q*4+2]);
            acc1[q*4+2] = fmaf(a1, w4.z, acc1[q*4+2]);
            acc0[q*4+3] = fmaf(a0, w4.w, acc0[q*4+3]);
            acc1[q*4+3] = fmaf(a1, w4.w, acc1[q*4+3]);
        }
    }

#pragma unroll
    for (int j = 0; j < 36; j++) {
        int oo = j / 9, n = j - oo * 9;
        float* Yp = g_Y + (size_t)(((o0 + oo) * NT + n) * Bb + b) * HW;
        Yp[p0]       = acc0[j];
        Yp[p0 + 256] = acc1[j];
    }
}

// ---------------------------------------------------------------------------
// Kernel B: pre-BN output = bias[o] + sum_n bilinear-blend(Y[o,n,b]),
// plus deterministic per-block BN partial sums.
// Grid: (HW/256=36, B=4, O=64)
// ---------------------------------------------------------------------------
struct alignas(16) Tap { int lo; int hi; float wl; float wr; };

__global__ __launch_bounds__(256) void kB(const float* __restrict__ frames,
                                          const float* __restrict__ bias,
                                          float* __restrict__ out) {
    __shared__ Tap SX[NT][Ww];
    __shared__ Tap SY[NT][Hh];
    __shared__ float rs[256], rq[256];

    const int o = blockIdx.z;
    const int b = blockIdx.y;

    // Precompute taps. idx < 864: x-direction; idx >= 864: y-direction.
    for (int idx = threadIdx.x; idx < 2 * NT * 96; idx += 256) {
        int which = (idx >= NT * 96) ? 1 : 0;
        int r = idx - which * (NT * 96);
        int n = r / 96, t = r - n * 96;
        float d  = frames[o * (2 * NT) + which * NT + n]; // first 9: x-offs, last 9: y-offs
        float pf = d + (float)t;                          // matches ref: frame + coord in f32
        float ff = floorf(pf);
        float lof = fminf(fmaxf(ff, 0.f), 95.f);
        float hif = fminf(fmaxf(ff + 1.f, 0.f), 95.f);
        float pc  = fminf(fmaxf(pf, 0.f), 95.f);
        Tap tp;
        tp.lo = (int)lof;
        tp.hi = (int)hif;
        tp.wl = 1.f + lof - pc;   // (1 + (lt - pc))
        tp.wr = 1.f - hif + pc;   // (1 - (rb - pc))
        if (which == 0) SX[n][t] = tp; else SY[n][t] = tp;
    }
    __syncthreads();

    const int p = blockIdx.x * 256 + threadIdx.x;
    const int h = p / Ww, w = p - h * Ww;
    const float* Ybase = g_Y + (size_t)(o * NT * Bb + b) * HW;

    float acc = 0.f;
#pragma unroll
    for (int n = 0; n < NT; n++) {
        Tap tx = SX[n][w];
        Tap ty = SY[n][h];
        const float* Yp = Ybase + (size_t)n * (Bb * HW);
        const float* rT = Yp + ty.lo * Ww;
        const float* rB = Yp + ty.hi * Ww;
        float vT = tx.wl * rT[tx.lo] + tx.wr * rT[tx.hi];
        float vB = tx.wl * rB[tx.lo] + tx.wr * rB[tx.hi];
        acc += ty.wl * vT + ty.wr * vB;
    }
    float v = acc + bias[o];
    out[(size_t)(b * Oo + o) * HW + p] = v;

    // Deterministic BN partials for this block
    rs[threadIdx.x] = v;
    rq[threadIdx.x] = v * v;
    __syncthreads();
    for (int st = 128; st > 0; st >>= 1) {
        if (threadIdx.x < st) {
            rs[threadIdx.x] += rs[threadIdx.x + st];
            rq[threadIdx.x] += rq[threadIdx.x + st];
        }
        __syncthreads();
    }
    if (threadIdx.x == 0) {
        int slot = (o * Bb + b) * NBX + blockIdx.x;
        g_psum[slot] = rs[0];
        g_psq [slot] = rq[0];
    }
}

// ---------------------------------------------------------------------------
// Kernel C1: reduce 144 partials per channel -> scale/shift. Grid: 64 blocks.
// ---------------------------------------------------------------------------
__global__ __launch_bounds__(256) void kC1(const float* __restrict__ gamma,
                                           const float* __restrict__ beta) {
    const int o = blockIdx.x;
    const int P = Bb * NBX;   // 144
    float s = 0.f, s2 = 0.f;
    if (threadIdx.x < P) {
        s  = g_psum[o * P + threadIdx.x];
        s2 = g_psq [o * P + threadIdx.x];
    }
    __shared__ float rs[256], rq[256];
    rs[threadIdx.x] = s;
    rq[threadIdx.x] = s2;
    __syncthreads();
    for (int st = 128; st > 0; st >>= 1) {
        if (threadIdx.x < st) {
            rs[threadIdx.x] += rs[threadIdx.x + st];
            rq[threadIdx.x] += rq[threadIdx.x + st];
        }
        __syncthreads();
    }
    if (threadIdx.x == 0) {
        const float inv = 1.f / (float)(Bb * HW);
        float mean = rs[0] * inv;
        float var  = rq[0] * inv - mean * mean;
        float rstd = rsqrtf(var + 1e-5f);
        float sc = gamma[o] * rstd;
        g_scale[o] = sc;
        g_shift[o] = beta[o] - mean * sc;
    }
}

// ---------------------------------------------------------------------------
// Kernel C2: in-place normalize + ReLU. Grid: 9216 blocks of 256.
// ---------------------------------------------------------------------------
__global__ __launch_bounds__(256) void kC2(float* __restrict__ out) {
    const int idx = blockIdx.x * 256 + threadIdx.x;
    const int o = (idx / HW) & 63;
    float v = out[idx];
    out[idx] = fmaxf(fmaf(v, g_scale[o], g_shift[o]), 0.f);
}

extern "C" void kernel_launch(void* const* d_in, const int* in_sizes, int n_in,
                              void* d_out, int out_size) {
    const float* x      = (const float*)d_in[0];
    const float* frames = (const float*)d_in[1];
    const float* cw     = (const float*)d_in[2];
    const float* cb     = (const float*)d_in[3];
    const float* gamma  = (const float*)d_in[4];
    const float* beta   = (const float*)d_in[5];
    float* out = (float*)d_out;

    kA<<<dim3(HW / 512, Bb, Oo / 4), 256>>>(x, cw);
    kB<<<dim3(HW / 256, Bb, Oo), 256>>>(frames, cb, out);
    kC1<<<Oo, 256>>>(gamma, beta);
    kC2<<<(Bb * Oo * HW) / 256, 256>>>(out);
}